// round 6
// baseline (speedup 1.0000x reference)
#include <cuda_runtime.h>
#include <cstdint>

// Scratch: __device__ globals (no allocation allowed).
#define NMAX 1000000
__device__ int   g_deg[NMAX];   // starts 0; each execution returns it to 0
__device__ float g_dinv[NMAX];
__device__ float g_xd[NMAX];    // dinv * x
__device__ float g_a1[NMAX];    // raw layer-1 accumulator (seeded with xd)
__device__ float g_yd[NMAX];    // dinv * y
__device__ float g_a2[NMAX];    // raw layer-2 accumulator (seeded with yd)

__device__ __forceinline__ float ldcg(const float* p) {
    float v;
    asm volatile("ld.global.cg.f32 %0, [%1];" : "=f"(v) : "l"(p));
    return v;
}

// ---------------------------------------------------------------------------
// Pass 1: deg[dst] += 1   (8 edges/thread, grid-stride)
__global__ void __launch_bounds__(256) k_deg(const int* __restrict__ dst, int E) {
    int nthreads = gridDim.x * blockDim.x;
    int tid = blockIdx.x * blockDim.x + threadIdx.x;
    int nv = E >> 3;
    for (int g = tid; g < nv; g += nthreads) {
        const int4* p = (const int4*)(dst + g * 8);
        int4 d0 = __ldcs(p);
        int4 d1 = __ldcs(p + 1);
        atomicAdd(&g_deg[d0.x], 1); atomicAdd(&g_deg[d0.y], 1);
        atomicAdd(&g_deg[d0.z], 1); atomicAdd(&g_deg[d0.w], 1);
        atomicAdd(&g_deg[d1.x], 1); atomicAdd(&g_deg[d1.y], 1);
        atomicAdd(&g_deg[d1.z], 1); atomicAdd(&g_deg[d1.w], 1);
    }
    for (int j = nv * 8 + tid; j < E; j += nthreads) atomicAdd(&g_deg[dst[j]], 1);
}

// ---------------------------------------------------------------------------
// Pass 2: dinv = rsqrt(deg+1); xd = dinv*x; seed a1 = xd; reset deg = 0
__global__ void __launch_bounds__(256) k_prep(const float* __restrict__ x, int n) {
    int i = blockIdx.x * blockDim.x + threadIdx.x;
    int base = i * 4;
    if (base + 3 < n) {
        int4   dg = *(const int4*)(g_deg + base);
        float4 xv = __ldcs((const float4*)(x + base));
        float4 di, xd;
        di.x = rsqrtf((float)(dg.x + 1)); di.y = rsqrtf((float)(dg.y + 1));
        di.z = rsqrtf((float)(dg.z + 1)); di.w = rsqrtf((float)(dg.w + 1));
        xd.x = di.x * xv.x; xd.y = di.y * xv.y; xd.z = di.z * xv.z; xd.w = di.w * xv.w;
        *(float4*)(g_dinv + base) = di;
        *(float4*)(g_xd  + base) = xd;
        *(float4*)(g_a1  + base) = xd;
        *(int4*)(g_deg + base) = make_int4(0, 0, 0, 0);
    } else {
        for (int j = base; j < n && j >= 0; j++) {
            float di = rsqrtf((float)(g_deg[j] + 1));
            g_dinv[j] = di;
            float xd = di * x[j];
            g_xd[j] = xd;
            g_a1[j] = xd;
            g_deg[j] = 0;
        }
    }
}

// ---------------------------------------------------------------------------
// Pass 3: a1[dst] += xd[src]   (8 edges/thread; globals referenced in device code)
__global__ void __launch_bounds__(256) k_edge1(const int* __restrict__ src,
                                               const int* __restrict__ dst, int E) {
    int nthreads = gridDim.x * blockDim.x;
    int tid = blockIdx.x * blockDim.x + threadIdx.x;
    int nv = E >> 3;
    for (int g = tid; g < nv; g += nthreads) {
        const int4* ps = (const int4*)(src + g * 8);
        const int4* pd = (const int4*)(dst + g * 8);
        int4 s0 = __ldcs(ps);
        int4 s1 = __ldcs(ps + 1);
        int4 d0 = __ldcs(pd);
        int4 d1 = __ldcs(pd + 1);
        float v0 = ldcg(&g_xd[s0.x]);
        float v1 = ldcg(&g_xd[s0.y]);
        float v2 = ldcg(&g_xd[s0.z]);
        float v3 = ldcg(&g_xd[s0.w]);
        float v4 = ldcg(&g_xd[s1.x]);
        float v5 = ldcg(&g_xd[s1.y]);
        float v6 = ldcg(&g_xd[s1.z]);
        float v7 = ldcg(&g_xd[s1.w]);
        atomicAdd(&g_a1[d0.x], v0); atomicAdd(&g_a1[d0.y], v1);
        atomicAdd(&g_a1[d0.z], v2); atomicAdd(&g_a1[d0.w], v3);
        atomicAdd(&g_a1[d1.x], v4); atomicAdd(&g_a1[d1.y], v5);
        atomicAdd(&g_a1[d1.z], v6); atomicAdd(&g_a1[d1.w], v7);
    }
    for (int j = nv * 8 + tid; j < E; j += nthreads)
        atomicAdd(&g_a1[dst[j]], ldcg(&g_xd[src[j]]));
}

// ---------------------------------------------------------------------------
// Pass 4: s1 = dinv*a1; MLP -> y; yd = dinv*y; seed a2 = yd
__device__ __forceinline__ float mlp8(float s, const float* W1, const float* b1,
                                      const float* W2) {
    float acc = 0.0f;
#pragma unroll
    for (int k = 0; k < 8; k++) {
        float h = fmaf(s, __ldg(&W1[k]), __ldg(&b1[k]));
        h = fmaxf(h, 0.0f);
        acc = fmaf(h, __ldg(&W2[k]), acc);
    }
    return acc;
}

__global__ void __launch_bounds__(256) k_node(const float* __restrict__ W1,
                                              const float* __restrict__ b1,
                                              const float* __restrict__ W2, int n) {
    int i = blockIdx.x * blockDim.x + threadIdx.x;
    int base = i * 4;
    if (base + 3 < n) {
        float4 di = *(const float4*)(g_dinv + base);
        float4 a  = *(const float4*)(g_a1 + base);
        float4 yd;
        yd.x = di.x * mlp8(di.x * a.x, W1, b1, W2);
        yd.y = di.y * mlp8(di.y * a.y, W1, b1, W2);
        yd.z = di.z * mlp8(di.z * a.z, W1, b1, W2);
        yd.w = di.w * mlp8(di.w * a.w, W1, b1, W2);
        *(float4*)(g_yd + base) = yd;
        *(float4*)(g_a2 + base) = yd;
    } else {
        for (int j = base; j < n && j >= 0; j++) {
            float di = g_dinv[j];
            float yd = di * mlp8(di * g_a1[j], W1, b1, W2);
            g_yd[j] = yd;
            g_a2[j] = yd;
        }
    }
}

// ---------------------------------------------------------------------------
// Pass 5: a2[dst] += yd[src]
__global__ void __launch_bounds__(256) k_edge2(const int* __restrict__ src,
                                               const int* __restrict__ dst, int E) {
    int nthreads = gridDim.x * blockDim.x;
    int tid = blockIdx.x * blockDim.x + threadIdx.x;
    int nv = E >> 3;
    for (int g = tid; g < nv; g += nthreads) {
        const int4* ps = (const int4*)(src + g * 8);
        const int4* pd = (const int4*)(dst + g * 8);
        int4 s0 = __ldcs(ps);
        int4 s1 = __ldcs(ps + 1);
        int4 d0 = __ldcs(pd);
        int4 d1 = __ldcs(pd + 1);
        float v0 = ldcg(&g_yd[s0.x]);
        float v1 = ldcg(&g_yd[s0.y]);
        float v2 = ldcg(&g_yd[s0.z]);
        float v3 = ldcg(&g_yd[s0.w]);
        float v4 = ldcg(&g_yd[s1.x]);
        float v5 = ldcg(&g_yd[s1.y]);
        float v6 = ldcg(&g_yd[s1.z]);
        float v7 = ldcg(&g_yd[s1.w]);
        atomicAdd(&g_a2[d0.x], v0); atomicAdd(&g_a2[d0.y], v1);
        atomicAdd(&g_a2[d0.z], v2); atomicAdd(&g_a2[d0.w], v3);
        atomicAdd(&g_a2[d1.x], v4); atomicAdd(&g_a2[d1.y], v5);
        atomicAdd(&g_a2[d1.z], v6); atomicAdd(&g_a2[d1.w], v7);
    }
    for (int j = nv * 8 + tid; j < E; j += nthreads)
        atomicAdd(&g_a2[dst[j]], ldcg(&g_yd[src[j]]));
}

// ---------------------------------------------------------------------------
// Pass 6: out = dinv*a2 + b2
__global__ void __launch_bounds__(256) k_final(const float* __restrict__ b2,
                                               float* __restrict__ out, int n) {
    int i = blockIdx.x * blockDim.x + threadIdx.x;
    int base = i * 4;
    float bb = __ldg(&b2[0]);
    if (base + 3 < n) {
        float4 di = *(const float4*)(g_dinv + base);
        float4 a  = *(const float4*)(g_a2 + base);
        float4 o;
        o.x = fmaf(di.x, a.x, bb);
        o.y = fmaf(di.y, a.y, bb);
        o.z = fmaf(di.z, a.z, bb);
        o.w = fmaf(di.w, a.w, bb);
        *(float4*)(out + base) = o;
    } else {
        for (int j = base; j < n && j >= 0; j++) out[j] = fmaf(g_dinv[j], g_a2[j], bb);
    }
}

// Scalar fallbacks (unaligned edge buffer)
__global__ void k_deg_s(const int* __restrict__ dst, int E) {
    int i = blockIdx.x * blockDim.x + threadIdx.x;
    if (i < E) atomicAdd(&g_deg[dst[i]], 1);
}
__global__ void k_edge1_s(const int* __restrict__ src, const int* __restrict__ dst, int E) {
    int i = blockIdx.x * blockDim.x + threadIdx.x;
    if (i < E) atomicAdd(&g_a1[dst[i]], ldcg(&g_xd[src[i]]));
}
__global__ void k_edge2_s(const int* __restrict__ src, const int* __restrict__ dst, int E) {
    int i = blockIdx.x * blockDim.x + threadIdx.x;
    if (i < E) atomicAdd(&g_a2[dst[i]], ldcg(&g_yd[src[i]]));
}

extern "C" void kernel_launch(void* const* d_in, const int* in_sizes, int n_in,
                              void* d_out, int out_size) {
    const float* x  = (const float*)d_in[0];
    const int*   ei = (const int*)d_in[1];     // [2, E]
    const float* W1 = (const float*)d_in[2];
    const float* b1 = (const float*)d_in[3];
    const float* W2 = (const float*)d_in[4];
    const float* b2 = (const float*)d_in[5];
    float* out = (float*)d_out;

    int n = in_sizes[0];           // 1,000,000
    int E = in_sizes[1] / 2;       // 10,000,000
    const int* src = ei;
    const int* dst = ei + E;

    const int T = 256;
    int gn4 = ((n + 3) / 4 + T - 1) / T;
    int gE8 = ((E >> 3) + T - 1) / T;
    if (gE8 > 148 * 32) gE8 = 148 * 32;   // grid-stride covers rest
    int gE  = (E + T - 1) / T;

    bool v4ok = ((E & 3) == 0) && ((((uintptr_t)ei) & 15) == 0);

    if (v4ok) {
        k_deg  <<<gE8, T>>>(dst, E);
        k_prep <<<gn4, T>>>(x, n);
        k_edge1<<<gE8, T>>>(src, dst, E);
        k_node <<<gn4, T>>>(W1, b1, W2, n);
        k_edge2<<<gE8, T>>>(src, dst, E);
        k_final<<<gn4, T>>>(b2, out, n);
    } else {
        k_deg_s  <<<gE, T>>>(dst, E);
        k_prep   <<<gn4, T>>>(x, n);
        k_edge1_s<<<gE, T>>>(src, dst, E);
        k_node   <<<gn4, T>>>(W1, b1, W2, n);
        k_edge2_s<<<gE, T>>>(src, dst, E);
        k_final  <<<gn4, T>>>(b2, out, n);
    }
}